// round 1
// baseline (speedup 1.0000x reference)
#include <cuda_runtime.h>
#include <cstdint>

// Problem constants
#define BATCH 2
#define SEQ   2048
#define DMODEL 1024
#define NHEADS 16
#define DHEAD 64
#define TOTDIM 1024          // NHEADS*DHEAD
#define E3 3072              // 3*TOTDIM
#define MTOT (BATCH*SEQ)     // 4096

// Scratch (static device globals — allowed; runtime alloc is not)
__device__ float g_qkv[(size_t)MTOT * E3];     // [4096, 3072]
__device__ float g_attn[(size_t)MTOT * TOTDIM]; // [4096, 1024]

// ---------------------------------------------------------------------------
// C[M,N] = A[M,K] @ B[N,K]^T   (both row-major, N-transposed weight layout)
// BM=BN=128, BK=8, 256 threads, 8x8 micro-tile per thread.
// M,N divisible by 128; K divisible by 8. No bounds checks needed here.
// ---------------------------------------------------------------------------
__global__ __launch_bounds__(256, 2)
void sgemm_nt(const float* __restrict__ A, const float* __restrict__ Bw,
              float* __restrict__ C, int M, int N, int K)
{
    __shared__ float As[8][128];
    __shared__ float Bs[8][128];

    const int tid = threadIdx.x;
    const int tx = tid & 15;         // 0..15  -> col group
    const int ty = tid >> 4;         // 0..15  -> row group
    const int row0 = blockIdx.y * 128;
    const int col0 = blockIdx.x * 128;

    const float* Ag = A  + (size_t)row0 * K;
    const float* Bg = Bw + (size_t)col0 * K;

    float acc[8][8];
#pragma unroll
    for (int i = 0; i < 8; ++i)
#pragma unroll
        for (int j = 0; j < 8; ++j) acc[i][j] = 0.f;

    const int lr = tid >> 1;         // 0..127 load row
    const int lc = (tid & 1) * 4;    // 0 or 4

    for (int k0 = 0; k0 < K; k0 += 8) {
        float4 av = *(const float4*)(Ag + (size_t)lr * K + k0 + lc);
        float4 bv = *(const float4*)(Bg + (size_t)lr * K + k0 + lc);
        As[lc+0][lr] = av.x; As[lc+1][lr] = av.y;
        As[lc+2][lr] = av.z; As[lc+3][lr] = av.w;
        Bs[lc+0][lr] = bv.x; Bs[lc+1][lr] = bv.y;
        Bs[lc+2][lr] = bv.z; Bs[lc+3][lr] = bv.w;
        __syncthreads();

#pragma unroll
        for (int k = 0; k < 8; ++k) {
            float a[8], b[8];
#pragma unroll
            for (int i = 0; i < 8; ++i) a[i] = As[k][ty*8 + i];
#pragma unroll
            for (int j = 0; j < 8; ++j) b[j] = Bs[k][tx*8 + j];
#pragma unroll
            for (int i = 0; i < 8; ++i)
#pragma unroll
                for (int j = 0; j < 8; ++j)
                    acc[i][j] += a[i] * b[j];
        }
        __syncthreads();
    }

#pragma unroll
    for (int i = 0; i < 8; ++i) {
        const int r = row0 + ty*8 + i;
#pragma unroll
        for (int j = 0; j < 8; j += 4) {
            float4 v = make_float4(acc[i][j], acc[i][j+1], acc[i][j+2], acc[i][j+3]);
            *(float4*)(C + (size_t)r * N + col0 + tx*8 + j) = v;
        }
    }
}

// ---------------------------------------------------------------------------
// Flash attention (causal), fp32. One block = 64 queries of one (b,h).
// Grid: (SEQ/64, BATCH*NHEADS). 256 threads, 4x4 micro-tiles.
// qkv layout: [b*SEQ + t][3072]; q at col h*64+d, k at 1024+..., v at 2048+...
// Output written as attn[(b*SEQ+t)*1024 + h*64 + d].
// ---------------------------------------------------------------------------
#define QPAD 68   // row pad for transposed Q/K and row-major V (272B, 16B aligned)
#define SPAD 65

__global__ __launch_bounds__(256, 1)
void attn_kernel(const float* __restrict__ qkv, float* __restrict__ attn)
{
    extern __shared__ float sm[];
    float* Qs   = sm;                  // [64][QPAD] transposed: Qs[d*QPAD + i]
    float* Ks   = Qs + 64*QPAD;        // [64][QPAD] transposed: Ks[d*QPAD + j]
    float* Vs   = Ks + 64*QPAD;        // [64][QPAD] row-major:  Vs[j*QPAD + d]
    float* Ss   = Vs + 64*QPAD;        // [64][SPAD]
    float* mrow = Ss + 64*SPAD;        // [64]
    float* lrow = mrow + 64;           // [64]
    float* frow = lrow + 64;           // [64]

    const int tid = threadIdx.x;
    const int tx = tid & 15;           // key/dim group
    const int ty = tid >> 4;           // query group
    const int qt = blockIdx.x;         // query tile 0..31
    const int bh = blockIdx.y;
    const int b  = bh >> 4;
    const int h  = bh & 15;
    const int qb = qt * 64;
    const float scale = 0.125f;        // 1/sqrt(64)

    const float* qbase = qkv + (size_t)(b*SEQ) * E3 + h*DHEAD;
    const float* kbase = qbase + TOTDIM;
    const float* vbase = qbase + 2*TOTDIM;

    // Load Q tile, transposed into Qs[d][i]
#pragma unroll
    for (int c = 0; c < 4; ++c) {
        int idx = c*256 + tid;                 // 1024 float4 chunks
        int r   = idx >> 4;                    // 0..63
        int d0  = (idx & 15) * 4;
        float4 v = *(const float4*)(qbase + (size_t)(qb + r) * E3 + d0);
        Qs[(d0+0)*QPAD + r] = v.x; Qs[(d0+1)*QPAD + r] = v.y;
        Qs[(d0+2)*QPAD + r] = v.z; Qs[(d0+3)*QPAD + r] = v.w;
    }
    if (tid < 64) { mrow[tid] = -1e30f; lrow[tid] = 0.f; }

    float acc[4][4];
#pragma unroll
    for (int i = 0; i < 4; ++i)
#pragma unroll
        for (int j = 0; j < 4; ++j) acc[i][j] = 0.f;

    for (int jt = 0; jt <= qt; ++jt) {
        const int kb = jt * 64;
        __syncthreads();   // protect Ks/Vs/Ss reuse from previous iteration

        // Load K (transposed) and V (row-major) tiles
#pragma unroll
        for (int c = 0; c < 4; ++c) {
            int idx = c*256 + tid;
            int r   = idx >> 4;
            int d0  = (idx & 15) * 4;
            float4 kv = *(const float4*)(kbase + (size_t)(kb + r) * E3 + d0);
            Ks[(d0+0)*QPAD + r] = kv.x; Ks[(d0+1)*QPAD + r] = kv.y;
            Ks[(d0+2)*QPAD + r] = kv.z; Ks[(d0+3)*QPAD + r] = kv.w;
            float4 vv = *(const float4*)(vbase + (size_t)(kb + r) * E3 + d0);
            *(float4*)(Vs + r*QPAD + d0) = vv;
        }
        __syncthreads();

        // S = Q @ K^T  (4x4 per thread)
        float s[4][4];
#pragma unroll
        for (int i = 0; i < 4; ++i)
#pragma unroll
            for (int j = 0; j < 4; ++j) s[i][j] = 0.f;

        for (int d = 0; d < 64; ++d) {
            float4 q4 = *(const float4*)(Qs + d*QPAD + ty*4);
            float4 k4 = *(const float4*)(Ks + d*QPAD + tx*4);
            float qv[4] = {q4.x, q4.y, q4.z, q4.w};
            float kv[4] = {k4.x, k4.y, k4.z, k4.w};
#pragma unroll
            for (int i = 0; i < 4; ++i)
#pragma unroll
                for (int j = 0; j < 4; ++j)
                    s[i][j] += qv[i] * kv[j];
        }

        // Mask + scale, stash to shared
#pragma unroll
        for (int i = 0; i < 4; ++i) {
            const int qi = qb + ty*4 + i;
#pragma unroll
            for (int j = 0; j < 4; ++j) {
                const int kj = kb + tx*4 + j;
                float v = (kj > qi) ? -1e30f : s[i][j] * scale;
                Ss[(ty*4 + i)*SPAD + tx*4 + j] = v;
            }
        }
        __syncthreads();

        // Online softmax per row (64 threads, one per row)
        if (tid < 64) {
            const int r = tid;
            float mo = mrow[r];
            float mn = mo;
            for (int j = 0; j < 64; ++j) mn = fmaxf(mn, Ss[r*SPAD + j]);
            float f = __expf(mo - mn);
            float l = lrow[r] * f;
            for (int j = 0; j < 64; ++j) {
                float p = __expf(Ss[r*SPAD + j] - mn);
                Ss[r*SPAD + j] = p;
                l += p;
            }
            mrow[r] = mn; lrow[r] = l; frow[r] = f;
        }
        __syncthreads();

        // O = O * f + P @ V
        float fr[4];
#pragma unroll
        for (int i = 0; i < 4; ++i) fr[i] = frow[ty*4 + i];
#pragma unroll
        for (int i = 0; i < 4; ++i)
#pragma unroll
            for (int j = 0; j < 4; ++j) acc[i][j] *= fr[i];

        for (int j = 0; j < 64; ++j) {
            float4 v4 = *(const float4*)(Vs + j*QPAD + tx*4);
            float vv[4] = {v4.x, v4.y, v4.z, v4.w};
            float p[4];
#pragma unroll
            for (int i = 0; i < 4; ++i) p[i] = Ss[(ty*4 + i)*SPAD + j];
#pragma unroll
            for (int i = 0; i < 4; ++i)
#pragma unroll
                for (int jj = 0; jj < 4; ++jj)
                    acc[i][jj] += p[i] * vv[jj];
        }
    }

    // Normalize and write out: attn[(b*SEQ + qb + i)][h*64 + d]
#pragma unroll
    for (int i = 0; i < 4; ++i) {
        const float inv = 1.0f / lrow[ty*4 + i];
        const size_t row = (size_t)(b*SEQ + qb + ty*4 + i) * TOTDIM + h*DHEAD + tx*4;
        float4 v = make_float4(acc[i][0]*inv, acc[i][1]*inv, acc[i][2]*inv, acc[i][3]*inv);
        *(float4*)(attn + row) = v;
    }
}

// ---------------------------------------------------------------------------
extern "C" void kernel_launch(void* const* d_in, const int* in_sizes, int n_in,
                              void* d_out, int out_size)
{
    const float* x    = (const float*)d_in[0];   // [2,2048,1024]
    const float* Wqkv = (const float*)d_in[1];   // [3072,1024]
    const float* Wout = (const float*)d_in[2];   // [1024,1024]
    float* out = (float*)d_out;                  // [2,2048,1024]

    float* qkv  = nullptr;
    float* attn = nullptr;
    cudaGetSymbolAddress((void**)&qkv,  g_qkv);
    cudaGetSymbolAddress((void**)&attn, g_attn);

    const int attn_smem = (3*64*QPAD + 64*SPAD + 3*64) * (int)sizeof(float);
    cudaFuncSetAttribute(attn_kernel,
                         cudaFuncAttributeMaxDynamicSharedMemorySize, attn_smem);

    // 1) qkv = x @ W_qkv^T : [4096,3072]
    sgemm_nt<<<dim3(E3/128, MTOT/128), 256>>>(x, Wqkv, qkv, MTOT, E3, DMODEL);

    // 2) causal attention -> attn [4096,1024]
    attn_kernel<<<dim3(SEQ/64, BATCH*NHEADS), 256, attn_smem>>>(qkv, attn);

    // 3) out = attn @ W_out^T : [4096,1024]
    sgemm_nt<<<dim3(TOTDIM/128, MTOT/128), 256>>>(attn, Wout, out, MTOT, TOTDIM, DMODEL);
}

// round 3
// speedup vs baseline: 1.5003x; 1.5003x over previous
#include <cuda_runtime.h>
#include <cuda_bf16.h>
#include <cstdint>

// Problem constants
#define BATCH 2
#define SEQ   2048
#define DMODEL 1024
#define NHEADS 16
#define DHEAD 64
#define TOTDIM 1024          // NHEADS*DHEAD
#define E3 3072              // 3*TOTDIM
#define MTOT (BATCH*SEQ)     // 4096

// ---------------------------------------------------------------------------
// Scratch (static device globals — runtime alloc is forbidden)
// ---------------------------------------------------------------------------
__device__ float g_qkv[(size_t)MTOT * E3];        // [4096,3072] fp32 (attention input)
__device__ float g_attn[(size_t)MTOT * TOTDIM];   // [4096,1024] fp32
__device__ __nv_bfloat16 g_xhi[(size_t)MTOT * DMODEL];
__device__ __nv_bfloat16 g_xlo[(size_t)MTOT * DMODEL];
__device__ __nv_bfloat16 g_wqhi[(size_t)E3 * DMODEL];
__device__ __nv_bfloat16 g_wqlo[(size_t)E3 * DMODEL];
__device__ __nv_bfloat16 g_wohi[(size_t)TOTDIM * DMODEL];
__device__ __nv_bfloat16 g_wolo[(size_t)TOTDIM * DMODEL];
__device__ __nv_bfloat16 g_ahi[(size_t)MTOT * TOTDIM];
__device__ __nv_bfloat16 g_alo[(size_t)MTOT * TOTDIM];

// ---------------------------------------------------------------------------
// Portable PTX helpers (no sm_103a-only features!)
// ---------------------------------------------------------------------------
__device__ __forceinline__ uint32_t smem_to_u32(const void* p) {
    uint32_t a;
    asm("{ .reg .u64 t; cvta.to.shared.u64 t, %1; cvt.u32.u64 %0, t; }" : "=r"(a) : "l"(p));
    return a;
}

__device__ __forceinline__ void ldmx4(uint32_t* r, uint32_t addr) {
    asm volatile("ldmatrix.sync.aligned.m8n8.x4.shared.b16 {%0,%1,%2,%3}, [%4];"
        : "=r"(r[0]), "=r"(r[1]), "=r"(r[2]), "=r"(r[3]) : "r"(addr));
}

__device__ __forceinline__ void mma_bf16(float* d, const uint32_t* a, uint32_t b0, uint32_t b1) {
    asm volatile("mma.sync.aligned.m16n8k16.row.col.f32.bf16.bf16.f32 "
        "{%0,%1,%2,%3}, {%4,%5,%6,%7}, {%8,%9}, {%0,%1,%2,%3};"
        : "+f"(d[0]), "+f"(d[1]), "+f"(d[2]), "+f"(d[3])
        : "r"(a[0]), "r"(a[1]), "r"(a[2]), "r"(a[3]), "r"(b0), "r"(b1));
}

// ---------------------------------------------------------------------------
// Split fp32 -> bf16 (hi, lo)
// ---------------------------------------------------------------------------
__global__ void split_bf16(const float* __restrict__ src, __nv_bfloat16* __restrict__ hi,
                           __nv_bfloat16* __restrict__ lo, int n4)
{
    int i = blockIdx.x * blockDim.x + threadIdx.x;
    if (i >= n4) return;
    float4 v = ((const float4*)src)[i];
    float xs[4] = {v.x, v.y, v.z, v.w};
    __nv_bfloat16 h[4], l[4];
#pragma unroll
    for (int k = 0; k < 4; ++k) {
        h[k] = __float2bfloat16(xs[k]);
        l[k] = __float2bfloat16(xs[k] - __bfloat162float(h[k]));
    }
    ((ushort4*)hi)[i] = make_ushort4(((ushort*)h)[0], ((ushort*)h)[1], ((ushort*)h)[2], ((ushort*)h)[3]);
    ((ushort4*)lo)[i] = make_ushort4(((ushort*)l)[0], ((ushort*)l)[1], ((ushort*)l)[2], ((ushort*)l)[3]);
}

// ---------------------------------------------------------------------------
// C[M,N] = Ahi@Bhi^T + Ahi@Blo^T + Alo@Bhi^T  via mma.sync bf16, fp32 accum.
// A: [M,K] row-major bf16; B: [N,K] row-major bf16 (= col-major for mma).
// CTA tile 128x128, K-chunk 64, 8 warps (2x4), warp tile 64x32.
// Smem: 4 tiles of [128 x 64] bf16 = 64 KB, XOR-swizzled (128B rows).
// ---------------------------------------------------------------------------
#define GSMEM (64 * 1024)

__global__ __launch_bounds__(256, 1)
void gemm_mma_bf16x3(const __nv_bfloat16* __restrict__ Ahi, const __nv_bfloat16* __restrict__ Alo,
                     const __nv_bfloat16* __restrict__ Bhi, const __nv_bfloat16* __restrict__ Blo,
                     float* __restrict__ C, int Nn, int K)
{
    extern __shared__ char sm[];
    char* pA_hi = sm;
    char* pA_lo = sm + 16384;
    char* pB_hi = sm + 32768;
    char* pB_lo = sm + 49152;
    const uint32_t sbase = smem_to_u32(sm);

    const int tid  = threadIdx.x;
    const int wid  = tid >> 5;
    const int lane = tid & 31;
    const int warp_m = wid & 1;      // 0..1  (64-row slabs)
    const int warp_n = wid >> 1;     // 0..3  (32-col slabs)
    const int row0 = blockIdx.y * 128;
    const int col0 = blockIdx.x * 128;

    const __nv_bfloat16* gAhi = Ahi + (size_t)row0 * K;
    const __nv_bfloat16* gAlo = Alo + (size_t)row0 * K;
    const __nv_bfloat16* gBhi = Bhi + (size_t)col0 * K;
    const __nv_bfloat16* gBlo = Blo + (size_t)col0 * K;

    float acc[4][4][4];
#pragma unroll
    for (int m = 0; m < 4; ++m)
#pragma unroll
        for (int n = 0; n < 4; ++n)
#pragma unroll
            for (int r = 0; r < 4; ++r) acc[m][n][r] = 0.f;

    // ldmatrix per-lane addressing: row-within-16, k-half
    const int ld_r = lane & 15;
    const int ld_k = (lane >> 4) * 16;   // byte offset (8 bf16)

    const int lrow = tid >> 3;           // 0..31 — loader: 32 rows per pass
    const int lcol = (tid & 7) * 16;     // byte col within 128B row

    for (int kc = 0; kc < K; kc += 64) {
        __syncthreads();   // previous compute done before overwriting tiles
#pragma unroll
        for (int i = 0; i < 4; ++i) {
            const int r = i * 32 + lrow;                    // 0..127
            uint32_t off = (uint32_t)(r * 128 + lcol);
            off ^= (uint32_t)((r & 7) << 4);                // XOR swizzle
            const size_t gofs = (size_t)r * K + kc;
            *(uint4*)(pA_hi + off) = *(const uint4*)((const char*)(gAhi + gofs) + lcol);
            *(uint4*)(pA_lo + off) = *(const uint4*)((const char*)(gAlo + gofs) + lcol);
            *(uint4*)(pB_hi + off) = *(const uint4*)((const char*)(gBhi + gofs) + lcol);
            *(uint4*)(pB_lo + off) = *(const uint4*)((const char*)(gBlo + gofs) + lcol);
        }
        __syncthreads();

#pragma unroll
        for (int ks = 0; ks < 4; ++ks) {
            uint32_t ahi[4][4], alo[4][4];
#pragma unroll
            for (int mt = 0; mt < 4; ++mt) {
                const int r = warp_m * 64 + mt * 16 + ld_r;
                uint32_t off = (uint32_t)(r * 128 + ks * 32 + ld_k);
                off ^= (uint32_t)((r & 7) << 4);
                ldmx4(ahi[mt], sbase + off);            // pA_hi at smem offset 0
                ldmx4(alo[mt], sbase + 16384 + off);
            }
            uint32_t bhi[2][4], blo[2][4];
#pragma unroll
            for (int nt2 = 0; nt2 < 2; ++nt2) {
                const int r = warp_n * 32 + nt2 * 16 + ld_r;
                uint32_t off = (uint32_t)(r * 128 + ks * 32 + ld_k);
                off ^= (uint32_t)((r & 7) << 4);
                ldmx4(bhi[nt2], sbase + 32768 + off);
                ldmx4(blo[nt2], sbase + 49152 + off);
            }
#pragma unroll
            for (int mt = 0; mt < 4; ++mt) {
#pragma unroll
                for (int nt = 0; nt < 4; ++nt) {
                    const int n2 = nt >> 1, nb = nt & 1;
                    mma_bf16(acc[mt][nt], ahi[mt], bhi[n2][nb], bhi[n2][nb + 2]);
                    mma_bf16(acc[mt][nt], ahi[mt], blo[n2][nb], blo[n2][nb + 2]);
                    mma_bf16(acc[mt][nt], alo[mt], bhi[n2][nb], bhi[n2][nb + 2]);
                }
            }
        }
    }

    // Epilogue: fragment layout -> C
    const int grp = lane >> 2;       // row within 8
    const int qid = (lane & 3) * 2;  // col pair
#pragma unroll
    for (int mt = 0; mt < 4; ++mt) {
        const int gm = row0 + warp_m * 64 + mt * 16 + grp;
#pragma unroll
        for (int nt = 0; nt < 4; ++nt) {
            const int gn = col0 + warp_n * 32 + nt * 8 + qid;
            *(float2*)(C + (size_t)gm * Nn + gn)       = make_float2(acc[mt][nt][0], acc[mt][nt][1]);
            *(float2*)(C + (size_t)(gm + 8) * Nn + gn) = make_float2(acc[mt][nt][2], acc[mt][nt][3]);
        }
    }
}

// ---------------------------------------------------------------------------
// Flash attention (causal), fp32 — unchanged (R1, known-correct)
// ---------------------------------------------------------------------------
#define QPAD 68
#define SPAD 65

__global__ __launch_bounds__(256, 1)
void attn_kernel(const float* __restrict__ qkv, float* __restrict__ attn)
{
    extern __shared__ float smf[];
    float* Qs   = smf;
    float* Ks   = Qs + 64*QPAD;
    float* Vs   = Ks + 64*QPAD;
    float* Ss   = Vs + 64*QPAD;
    float* mrow = Ss + 64*SPAD;
    float* lrow = mrow + 64;
    float* frow = lrow + 64;

    const int tid = threadIdx.x;
    const int tx = tid & 15;
    const int ty = tid >> 4;
    const int qt = blockIdx.x;
    const int bh = blockIdx.y;
    const int b  = bh >> 4;
    const int h  = bh & 15;
    const int qb = qt * 64;
    const float scale = 0.125f;

    const float* qbase = qkv + (size_t)(b*SEQ) * E3 + h*DHEAD;
    const float* kbase = qbase + TOTDIM;
    const float* vbase = qbase + 2*TOTDIM;

#pragma unroll
    for (int c = 0; c < 4; ++c) {
        int idx = c*256 + tid;
        int r   = idx >> 4;
        int d0  = (idx & 15) * 4;
        float4 v = *(const float4*)(qbase + (size_t)(qb + r) * E3 + d0);
        Qs[(d0+0)*QPAD + r] = v.x; Qs[(d0+1)*QPAD + r] = v.y;
        Qs[(d0+2)*QPAD + r] = v.z; Qs[(d0+3)*QPAD + r] = v.w;
    }
    if (tid < 64) { mrow[tid] = -1e30f; lrow[tid] = 0.f; }

    float acc[4][4];
#pragma unroll
    for (int i = 0; i < 4; ++i)
#pragma unroll
        for (int j = 0; j < 4; ++j) acc[i][j] = 0.f;

    for (int jt = 0; jt <= qt; ++jt) {
        const int kb = jt * 64;
        __syncthreads();

#pragma unroll
        for (int c = 0; c < 4; ++c) {
            int idx = c*256 + tid;
            int r   = idx >> 4;
            int d0  = (idx & 15) * 4;
            float4 kv = *(const float4*)(kbase + (size_t)(kb + r) * E3 + d0);
            Ks[(d0+0)*QPAD + r] = kv.x; Ks[(d0+1)*QPAD + r] = kv.y;
            Ks[(d0+2)*QPAD + r] = kv.z; Ks[(d0+3)*QPAD + r] = kv.w;
            float4 vv = *(const float4*)(vbase + (size_t)(kb + r) * E3 + d0);
            *(float4*)(Vs + r*QPAD + d0) = vv;
        }
        __syncthreads();

        float s[4][4];
#pragma unroll
        for (int i = 0; i < 4; ++i)
#pragma unroll
            for (int j = 0; j < 4; ++j) s[i][j] = 0.f;

        for (int d = 0; d < 64; ++d) {
            float4 q4 = *(const float4*)(Qs + d*QPAD + ty*4);
            float4 k4 = *(const float4*)(Ks + d*QPAD + tx*4);
            float qv[4] = {q4.x, q4.y, q4.z, q4.w};
            float kv[4] = {k4.x, k4.y, k4.z, k4.w};
#pragma unroll
            for (int i = 0; i < 4; ++i)
#pragma unroll
                for (int j = 0; j < 4; ++j)
                    s[i][j] += qv[i] * kv[j];
        }

#pragma unroll
        for (int i = 0; i < 4; ++i) {
            const int qi = qb + ty*4 + i;
#pragma unroll
            for (int j = 0; j < 4; ++j) {
                const int kj = kb + tx*4 + j;
                float v = (kj > qi) ? -1e30f : s[i][j] * scale;
                Ss[(ty*4 + i)*SPAD + tx*4 + j] = v;
            }
        }
        __syncthreads();

        if (tid < 64) {
            const int r = tid;
            float mo = mrow[r];
            float mn = mo;
            for (int j = 0; j < 64; ++j) mn = fmaxf(mn, Ss[r*SPAD + j]);
            float f = __expf(mo - mn);
            float l = lrow[r] * f;
            for (int j = 0; j < 64; ++j) {
                float p = __expf(Ss[r*SPAD + j] - mn);
                Ss[r*SPAD + j] = p;
                l += p;
            }
            mrow[r] = mn; lrow[r] = l; frow[r] = f;
        }
        __syncthreads();

        float fr[4];
#pragma unroll
        for (int i = 0; i < 4; ++i) fr[i] = frow[ty*4 + i];
#pragma unroll
        for (int i = 0; i < 4; ++i)
#pragma unroll
            for (int j = 0; j < 4; ++j) acc[i][j] *= fr[i];

        for (int j = 0; j < 64; ++j) {
            float4 v4 = *(const float4*)(Vs + j*QPAD + tx*4);
            float vv[4] = {v4.x, v4.y, v4.z, v4.w};
            float p[4];
#pragma unroll
            for (int i = 0; i < 4; ++i) p[i] = Ss[(ty*4 + i)*SPAD + j];
#pragma unroll
            for (int i = 0; i < 4; ++i)
#pragma unroll
                for (int jj = 0; jj < 4; ++jj)
                    acc[i][jj] += p[i] * vv[jj];
        }
    }

#pragma unroll
    for (int i = 0; i < 4; ++i) {
        const float inv = 1.0f / lrow[ty*4 + i];
        const size_t row = (size_t)(b*SEQ + qb + ty*4 + i) * TOTDIM + h*DHEAD + tx*4;
        float4 v = make_float4(acc[i][0]*inv, acc[i][1]*inv, acc[i][2]*inv, acc[i][3]*inv);
        *(float4*)(attn + row) = v;
    }
}

// ---------------------------------------------------------------------------
extern "C" void kernel_launch(void* const* d_in, const int* in_sizes, int n_in,
                              void* d_out, int out_size)
{
    const float* x    = (const float*)d_in[0];   // [2,2048,1024]
    const float* Wqkv = (const float*)d_in[1];   // [3072,1024]
    const float* Wout = (const float*)d_in[2];   // [1024,1024]
    float* out = (float*)d_out;                  // [2,2048,1024]

    float *qkv, *attn;
    __nv_bfloat16 *xhi, *xlo, *wqhi, *wqlo, *wohi, *wolo, *ahi, *alo;
    cudaGetSymbolAddress((void**)&qkv,  g_qkv);
    cudaGetSymbolAddress((void**)&attn, g_attn);
    cudaGetSymbolAddress((void**)&xhi,  g_xhi);
    cudaGetSymbolAddress((void**)&xlo,  g_xlo);
    cudaGetSymbolAddress((void**)&wqhi, g_wqhi);
    cudaGetSymbolAddress((void**)&wqlo, g_wqlo);
    cudaGetSymbolAddress((void**)&wohi, g_wohi);
    cudaGetSymbolAddress((void**)&wolo, g_wolo);
    cudaGetSymbolAddress((void**)&ahi,  g_ahi);
    cudaGetSymbolAddress((void**)&alo,  g_alo);

    cudaFuncSetAttribute(gemm_mma_bf16x3, cudaFuncAttributeMaxDynamicSharedMemorySize, GSMEM);
    const int attn_smem = (3*64*QPAD + 64*SPAD + 3*64) * (int)sizeof(float);
    cudaFuncSetAttribute(attn_kernel, cudaFuncAttributeMaxDynamicSharedMemorySize, attn_smem);

    // Split inputs to bf16 hi/lo
    {
        int n4 = MTOT * DMODEL / 4;
        split_bf16<<<(n4 + 255) / 256, 256>>>(x, xhi, xlo, n4);
        n4 = E3 * DMODEL / 4;
        split_bf16<<<(n4 + 255) / 256, 256>>>(Wqkv, wqhi, wqlo, n4);
        n4 = TOTDIM * DMODEL / 4;
        split_bf16<<<(n4 + 255) / 256, 256>>>(Wout, wohi, wolo, n4);
    }

    // 1) qkv = x @ Wqkv^T : [4096, 3072]
    gemm_mma_bf16x3<<<dim3(E3/128, MTOT/128), 256, GSMEM>>>(xhi, xlo, wqhi, wqlo, qkv, E3, DMODEL);

    // 2) causal attention -> attn [4096, 1024]
    attn_kernel<<<dim3(SEQ/64, BATCH*NHEADS), 256, attn_smem>>>(qkv, attn);

    // split attention output
    {
        int n4 = MTOT * TOTDIM / 4;
        split_bf16<<<(n4 + 255) / 256, 256>>>(attn, ahi, alo, n4);
    }

    // 3) out = attn @ Wout^T : [4096, 1024]
    gemm_mma_bf16x3<<<dim3(TOTDIM/128, MTOT/128), 256, GSMEM>>>(ahi, alo, wohi, wolo, out, TOTDIM, DMODEL);
}

// round 4
// speedup vs baseline: 2.4756x; 1.6501x over previous
#include <cuda_runtime.h>
#include <cuda_bf16.h>
#include <cstdint>

// Problem constants
#define BATCH 2
#define SEQ   2048
#define DMODEL 1024
#define NHEADS 16
#define DHEAD 64
#define TOTDIM 1024          // NHEADS*DHEAD
#define E3 3072              // 3*TOTDIM
#define MTOT (BATCH*SEQ)     // 4096

// ---------------------------------------------------------------------------
// Scratch (static device globals — runtime alloc is forbidden)
// ---------------------------------------------------------------------------
__device__ float g_qkv[(size_t)MTOT * E3];        // [4096,3072] fp32 (attention input)
__device__ __nv_bfloat16 g_xhi[(size_t)MTOT * DMODEL];
__device__ __nv_bfloat16 g_xlo[(size_t)MTOT * DMODEL];
__device__ __nv_bfloat16 g_wqhi[(size_t)E3 * DMODEL];
__device__ __nv_bfloat16 g_wqlo[(size_t)E3 * DMODEL];
__device__ __nv_bfloat16 g_wohi[(size_t)TOTDIM * DMODEL];
__device__ __nv_bfloat16 g_wolo[(size_t)TOTDIM * DMODEL];
__device__ __nv_bfloat16 g_ahi[(size_t)MTOT * TOTDIM];
__device__ __nv_bfloat16 g_alo[(size_t)MTOT * TOTDIM];

// ---------------------------------------------------------------------------
// Portable PTX helpers (no sm_103a-only features)
// ---------------------------------------------------------------------------
__device__ __forceinline__ uint32_t smem_to_u32(const void* p) {
    uint32_t a;
    asm("{ .reg .u64 t; cvta.to.shared.u64 t, %1; cvt.u32.u64 %0, t; }" : "=r"(a) : "l"(p));
    return a;
}

__device__ __forceinline__ void ldmx4(uint32_t* r, uint32_t addr) {
    asm volatile("ldmatrix.sync.aligned.m8n8.x4.shared.b16 {%0,%1,%2,%3}, [%4];"
        : "=r"(r[0]), "=r"(r[1]), "=r"(r[2]), "=r"(r[3]) : "r"(addr));
}

__device__ __forceinline__ void ldmx4t(uint32_t* r, uint32_t addr) {
    asm volatile("ldmatrix.sync.aligned.m8n8.x4.trans.shared.b16 {%0,%1,%2,%3}, [%4];"
        : "=r"(r[0]), "=r"(r[1]), "=r"(r[2]), "=r"(r[3]) : "r"(addr));
}

__device__ __forceinline__ void mma_bf16(float* d, const uint32_t* a, uint32_t b0, uint32_t b1) {
    asm volatile("mma.sync.aligned.m16n8k16.row.col.f32.bf16.bf16.f32 "
        "{%0,%1,%2,%3}, {%4,%5,%6,%7}, {%8,%9}, {%0,%1,%2,%3};"
        : "+f"(d[0]), "+f"(d[1]), "+f"(d[2]), "+f"(d[3])
        : "r"(a[0]), "r"(a[1]), "r"(a[2]), "r"(a[3]), "r"(b0), "r"(b1));
}

// Split two floats into packed bf16x2 hi + bf16x2 lo (residual)
__device__ __forceinline__ void split2(float x, float y, uint32_t& hi, uint32_t& lo) {
    __nv_bfloat16 hx = __float2bfloat16(x), hy = __float2bfloat16(y);
    float rx = x - __bfloat162float(hx), ry = y - __bfloat162float(hy);
    __nv_bfloat16 lx = __float2bfloat16(rx), ly = __float2bfloat16(ry);
    hi = ((uint32_t)*(uint16_t*)&hy << 16) | (uint32_t)*(uint16_t*)&hx;
    lo = ((uint32_t)*(uint16_t*)&ly << 16) | (uint32_t)*(uint16_t*)&lx;
}

#define SWZ(r, off) ((uint32_t)(off) ^ (uint32_t)(((r) & 7) << 4))

// ---------------------------------------------------------------------------
// Split fp32 -> bf16 (hi, lo)
// ---------------------------------------------------------------------------
__global__ void split_bf16(const float* __restrict__ src, __nv_bfloat16* __restrict__ hi,
                           __nv_bfloat16* __restrict__ lo, int n4)
{
    int i = blockIdx.x * blockDim.x + threadIdx.x;
    if (i >= n4) return;
    float4 v = ((const float4*)src)[i];
    float xs[4] = {v.x, v.y, v.z, v.w};
    __nv_bfloat16 h[4], l[4];
#pragma unroll
    for (int k = 0; k < 4; ++k) {
        h[k] = __float2bfloat16(xs[k]);
        l[k] = __float2bfloat16(xs[k] - __bfloat162float(h[k]));
    }
    ((ushort4*)hi)[i] = make_ushort4(((ushort*)h)[0], ((ushort*)h)[1], ((ushort*)h)[2], ((ushort*)h)[3]);
    ((ushort4*)lo)[i] = make_ushort4(((ushort*)l)[0], ((ushort*)l)[1], ((ushort*)l)[2], ((ushort*)l)[3]);
}

// ---------------------------------------------------------------------------
// GEMM (unchanged from R3): C = Ahi@Bhi^T + Ahi@Blo^T + Alo@Bhi^T
// ---------------------------------------------------------------------------
#define GSMEM (64 * 1024)

__global__ __launch_bounds__(256, 1)
void gemm_mma_bf16x3(const __nv_bfloat16* __restrict__ Ahi, const __nv_bfloat16* __restrict__ Alo,
                     const __nv_bfloat16* __restrict__ Bhi, const __nv_bfloat16* __restrict__ Blo,
                     float* __restrict__ C, int Nn, int K)
{
    extern __shared__ char sm[];
    char* pA_hi = sm;
    char* pA_lo = sm + 16384;
    char* pB_hi = sm + 32768;
    char* pB_lo = sm + 49152;
    const uint32_t sbase = smem_to_u32(sm);

    const int tid  = threadIdx.x;
    const int wid  = tid >> 5;
    const int lane = tid & 31;
    const int warp_m = wid & 1;
    const int warp_n = wid >> 1;
    const int row0 = blockIdx.y * 128;
    const int col0 = blockIdx.x * 128;

    const __nv_bfloat16* gAhi = Ahi + (size_t)row0 * K;
    const __nv_bfloat16* gAlo = Alo + (size_t)row0 * K;
    const __nv_bfloat16* gBhi = Bhi + (size_t)col0 * K;
    const __nv_bfloat16* gBlo = Blo + (size_t)col0 * K;

    float acc[4][4][4];
#pragma unroll
    for (int m = 0; m < 4; ++m)
#pragma unroll
        for (int n = 0; n < 4; ++n)
#pragma unroll
            for (int r = 0; r < 4; ++r) acc[m][n][r] = 0.f;

    const int ld_r = lane & 15;
    const int ld_k = (lane >> 4) * 16;
    const int lrow = tid >> 3;
    const int lcol = (tid & 7) * 16;

    for (int kc = 0; kc < K; kc += 64) {
        __syncthreads();
#pragma unroll
        for (int i = 0; i < 4; ++i) {
            const int r = i * 32 + lrow;
            uint32_t off = SWZ(r, r * 128 + lcol);
            const size_t gofs = (size_t)r * K + kc;
            *(uint4*)(pA_hi + off) = *(const uint4*)((const char*)(gAhi + gofs) + lcol);
            *(uint4*)(pA_lo + off) = *(const uint4*)((const char*)(gAlo + gofs) + lcol);
            *(uint4*)(pB_hi + off) = *(const uint4*)((const char*)(gBhi + gofs) + lcol);
            *(uint4*)(pB_lo + off) = *(const uint4*)((const char*)(gBlo + gofs) + lcol);
        }
        __syncthreads();

#pragma unroll
        for (int ks = 0; ks < 4; ++ks) {
            uint32_t ahi[4][4], alo[4][4];
#pragma unroll
            for (int mt = 0; mt < 4; ++mt) {
                const int r = warp_m * 64 + mt * 16 + ld_r;
                uint32_t off = SWZ(r, r * 128 + ks * 32 + ld_k);
                ldmx4(ahi[mt], sbase + off);
                ldmx4(alo[mt], sbase + 16384 + off);
            }
            uint32_t bhi[2][4], blo[2][4];
#pragma unroll
            for (int nt2 = 0; nt2 < 2; ++nt2) {
                const int r = warp_n * 32 + nt2 * 16 + ld_r;
                uint32_t off = SWZ(r, r * 128 + ks * 32 + ld_k);
                ldmx4(bhi[nt2], sbase + 32768 + off);
                ldmx4(blo[nt2], sbase + 49152 + off);
            }
#pragma unroll
            for (int mt = 0; mt < 4; ++mt) {
#pragma unroll
                for (int nt = 0; nt < 4; ++nt) {
                    const int n2 = nt >> 1, nb = nt & 1;
                    mma_bf16(acc[mt][nt], ahi[mt], bhi[n2][nb], bhi[n2][nb + 2]);
                    mma_bf16(acc[mt][nt], ahi[mt], blo[n2][nb], blo[n2][nb + 2]);
                    mma_bf16(acc[mt][nt], alo[mt], bhi[n2][nb], bhi[n2][nb + 2]);
                }
            }
        }
    }

    const int grp = lane >> 2;
    const int qid = (lane & 3) * 2;
#pragma unroll
    for (int mt = 0; mt < 4; ++mt) {
        const int gm = row0 + warp_m * 64 + mt * 16 + grp;
#pragma unroll
        for (int nt = 0; nt < 4; ++nt) {
            const int gn = col0 + warp_n * 32 + nt * 8 + qid;
            *(float2*)(C + (size_t)gm * Nn + gn)       = make_float2(acc[mt][nt][0], acc[mt][nt][1]);
            *(float2*)(C + (size_t)(gm + 8) * Nn + gn) = make_float2(acc[mt][nt][2], acc[mt][nt][3]);
        }
    }
}

// ---------------------------------------------------------------------------
// Tensor-core flash attention (causal), bf16x3 hi/lo, fp32 accum.
// 128 threads = 4 warps; warp w owns q-rows [qb + 16w, +16). 64-key tiles.
// Writes bf16 hi/lo output directly (input to out-proj GEMM).
// ---------------------------------------------------------------------------
__global__ __launch_bounds__(128)
void attn_mma(const float* __restrict__ qkv,
              __nv_bfloat16* __restrict__ ahi, __nv_bfloat16* __restrict__ alo)
{
    __shared__ char sm[49152];
    const uint32_t sb = smem_to_u32(sm);
    // [64 rows][128B] each, XOR-swizzled
    const uint32_t oQh = 0, oQl = 8192, oKh = 16384, oKl = 24576, oVh = 32768, oVl = 40960;

    const int tid = threadIdx.x;
    const int wid = tid >> 5, lane = tid & 31;
    const int grp = lane >> 2, qid = lane & 3;
    const int qt = blockIdx.x, bh = blockIdx.y;
    const int b = bh >> 4, h = bh & 15;
    const int qb = qt * 64;
    const int qr = wid * 16;

    const float* qbase = qkv + (size_t)(b * SEQ) * E3 + h * DHEAD;
    const float* kbase = qbase + TOTDIM;
    const float* vbase = qbase + 2 * TOTDIM;

    // ---- Load Q (scaled by 1/sqrt(Dh)), split hi/lo into smem ----
#pragma unroll
    for (int i = 0; i < 8; ++i) {
        int idx = i * 128 + tid;
        int r = idx >> 4, d0 = (idx & 15) * 4;
        float4 v = *(const float4*)(qbase + (size_t)(qb + r) * E3 + d0);
        v.x *= 0.125f; v.y *= 0.125f; v.z *= 0.125f; v.w *= 0.125f;
        uint32_t h0, l0p, h1, l1p;
        split2(v.x, v.y, h0, l0p);
        split2(v.z, v.w, h1, l1p);
        uint32_t off = SWZ(r, r * 128 + d0 * 2);
        *(uint2*)(sm + oQh + off) = make_uint2(h0, h1);
        *(uint2*)(sm + oQl + off) = make_uint2(l0p, l1p);
    }
    __syncthreads();

    // ---- Hoist Q A-fragments ----
    uint32_t aqh[4][4], aql[4][4];
    {
        const int r = qr + (lane & 15);
        const int ch = (lane >> 4) << 4;
#pragma unroll
        for (int ks = 0; ks < 4; ++ks) {
            uint32_t off = SWZ(r, r * 128 + ks * 32 + ch);
            ldmx4(aqh[ks], sb + oQh + off);
            ldmx4(aql[ks], sb + oQl + off);
        }
    }

    float o[8][4];
#pragma unroll
    for (int nd = 0; nd < 8; ++nd)
#pragma unroll
        for (int i = 0; i < 4; ++i) o[nd][i] = 0.f;
    float m0 = -1e30f, m1 = -1e30f, l0 = 0.f, l1 = 0.f;

    for (int jt = 0; jt <= qt; ++jt) {
        const int kb = jt * 64;
        __syncthreads();
        // ---- Load K, V tiles, split hi/lo ----
#pragma unroll
        for (int i = 0; i < 8; ++i) {
            int idx = i * 128 + tid;
            int r = idx >> 4, d0 = (idx & 15) * 4;
            uint32_t off = SWZ(r, r * 128 + d0 * 2);
            float4 kv = *(const float4*)(kbase + (size_t)(kb + r) * E3 + d0);
            uint32_t h0, l0p, h1, l1p;
            split2(kv.x, kv.y, h0, l0p);
            split2(kv.z, kv.w, h1, l1p);
            *(uint2*)(sm + oKh + off) = make_uint2(h0, h1);
            *(uint2*)(sm + oKl + off) = make_uint2(l0p, l1p);
            float4 vv = *(const float4*)(vbase + (size_t)(kb + r) * E3 + d0);
            split2(vv.x, vv.y, h0, l0p);
            split2(vv.z, vv.w, h1, l1p);
            *(uint2*)(sm + oVh + off) = make_uint2(h0, h1);
            *(uint2*)(sm + oVl + off) = make_uint2(l0p, l1p);
        }
        __syncthreads();

        // ---- S = Q @ K^T (3-pass bf16) ----
        float s[8][4];
#pragma unroll
        for (int nb = 0; nb < 8; ++nb)
#pragma unroll
            for (int i = 0; i < 4; ++i) s[nb][i] = 0.f;
        {
            const int rB = lane & 15;
            const int chB = (lane >> 4) << 4;
#pragma unroll
            for (int ks = 0; ks < 4; ++ks) {
                uint32_t kh[4][4], kl[4][4];
#pragma unroll
                for (int nt2 = 0; nt2 < 4; ++nt2) {
                    const int r = nt2 * 16 + rB;
                    uint32_t off = SWZ(r, r * 128 + ks * 32 + chB);
                    ldmx4(kh[nt2], sb + oKh + off);
                    ldmx4(kl[nt2], sb + oKl + off);
                }
#pragma unroll
                for (int nt2 = 0; nt2 < 4; ++nt2)
#pragma unroll
                    for (int j = 0; j < 2; ++j) {
                        const int nb = nt2 * 2 + j;
                        mma_bf16(s[nb], aqh[ks], kh[nt2][j], kh[nt2][j + 2]);
                        mma_bf16(s[nb], aqh[ks], kl[nt2][j], kl[nt2][j + 2]);
                        mma_bf16(s[nb], aql[ks], kh[nt2][j], kh[nt2][j + 2]);
                    }
            }
        }

        // ---- Causal mask (diagonal tile only) ----
        if (jt == qt) {
            const int row0g = qb + qr + grp;
            const int row1g = row0g + 8;
#pragma unroll
            for (int nb = 0; nb < 8; ++nb) {
                const int c0 = kb + nb * 8 + qid * 2;
                if (c0 > row0g)     s[nb][0] = -1e30f;
                if (c0 + 1 > row0g) s[nb][1] = -1e30f;
                if (c0 > row1g)     s[nb][2] = -1e30f;
                if (c0 + 1 > row1g) s[nb][3] = -1e30f;
            }
        }

        // ---- Online softmax ----
        float mx0 = -1e30f, mx1 = -1e30f;
#pragma unroll
        for (int nb = 0; nb < 8; ++nb) {
            mx0 = fmaxf(mx0, fmaxf(s[nb][0], s[nb][1]));
            mx1 = fmaxf(mx1, fmaxf(s[nb][2], s[nb][3]));
        }
        mx0 = fmaxf(mx0, __shfl_xor_sync(0xffffffffu, mx0, 1));
        mx0 = fmaxf(mx0, __shfl_xor_sync(0xffffffffu, mx0, 2));
        mx1 = fmaxf(mx1, __shfl_xor_sync(0xffffffffu, mx1, 1));
        mx1 = fmaxf(mx1, __shfl_xor_sync(0xffffffffu, mx1, 2));
        const float mn0 = fmaxf(m0, mx0), mn1 = fmaxf(m1, mx1);
        const float f0 = __expf(m0 - mn0), f1 = __expf(m1 - mn1);
        m0 = mn0; m1 = mn1;
        float sum0 = 0.f, sum1 = 0.f;
#pragma unroll
        for (int nb = 0; nb < 8; ++nb) {
            s[nb][0] = __expf(s[nb][0] - m0); sum0 += s[nb][0];
            s[nb][1] = __expf(s[nb][1] - m0); sum0 += s[nb][1];
            s[nb][2] = __expf(s[nb][2] - m1); sum1 += s[nb][2];
            s[nb][3] = __expf(s[nb][3] - m1); sum1 += s[nb][3];
        }
        sum0 += __shfl_xor_sync(0xffffffffu, sum0, 1);
        sum0 += __shfl_xor_sync(0xffffffffu, sum0, 2);
        sum1 += __shfl_xor_sync(0xffffffffu, sum1, 1);
        sum1 += __shfl_xor_sync(0xffffffffu, sum1, 2);
        l0 = l0 * f0 + sum0;
        l1 = l1 * f1 + sum1;
#pragma unroll
        for (int nd = 0; nd < 8; ++nd) {
            o[nd][0] *= f0; o[nd][1] *= f0;
            o[nd][2] *= f1; o[nd][3] *= f1;
        }

        // ---- P fragments (hi/lo) from S accumulators ----
        uint32_t ph[4][4], pl[4][4];
#pragma unroll
        for (int kp = 0; kp < 4; ++kp) {
            split2(s[2*kp][0],   s[2*kp][1],   ph[kp][0], pl[kp][0]);
            split2(s[2*kp][2],   s[2*kp][3],   ph[kp][1], pl[kp][1]);
            split2(s[2*kp+1][0], s[2*kp+1][1], ph[kp][2], pl[kp][2]);
            split2(s[2*kp+1][2], s[2*kp+1][3], ph[kp][3], pl[kp][3]);
        }

        // ---- O += P @ V (3-pass), V^T B-frags via ldmatrix.trans ----
        {
            const int tile = lane >> 3;
            const int ta = tile & 1, ndo = tile >> 1;
            const int rl = lane & 7;
#pragma unroll
            for (int kp = 0; kp < 4; ++kp) {
#pragma unroll
                for (int ndp = 0; ndp < 4; ++ndp) {
                    const int r = kp * 16 + ta * 8 + rl;
                    uint32_t off = SWZ(r, r * 128 + (ndp * 2 + ndo) * 16);
                    uint32_t vh[4], vl[4];
                    ldmx4t(vh, sb + oVh + off);
                    ldmx4t(vl, sb + oVl + off);
                    mma_bf16(o[ndp*2],   ph[kp], vh[0], vh[1]);
                    mma_bf16(o[ndp*2],   ph[kp], vl[0], vl[1]);
                    mma_bf16(o[ndp*2],   pl[kp], vh[0], vh[1]);
                    mma_bf16(o[ndp*2+1], ph[kp], vh[2], vh[3]);
                    mma_bf16(o[ndp*2+1], ph[kp], vl[2], vl[3]);
                    mma_bf16(o[ndp*2+1], pl[kp], vh[2], vh[3]);
                }
            }
        }
    }

    // ---- Epilogue: normalize, split hi/lo, store ----
    const float inv0 = 1.f / l0, inv1 = 1.f / l1;
    const int row0g = qb + qr + grp;
    const size_t base0 = (size_t)(b * SEQ + row0g) * TOTDIM + h * DHEAD;
    const size_t base1 = base0 + (size_t)8 * TOTDIM;
#pragma unroll
    for (int nd = 0; nd < 8; ++nd) {
        const int col = nd * 8 + qid * 2;
        uint32_t hh, ll;
        split2(o[nd][0] * inv0, o[nd][1] * inv0, hh, ll);
        *(uint32_t*)(ahi + base0 + col) = hh;
        *(uint32_t*)(alo + base0 + col) = ll;
        split2(o[nd][2] * inv1, o[nd][3] * inv1, hh, ll);
        *(uint32_t*)(ahi + base1 + col) = hh;
        *(uint32_t*)(alo + base1 + col) = ll;
    }
}

// ---------------------------------------------------------------------------
extern "C" void kernel_launch(void* const* d_in, const int* in_sizes, int n_in,
                              void* d_out, int out_size)
{
    const float* x    = (const float*)d_in[0];   // [2,2048,1024]
    const float* Wqkv = (const float*)d_in[1];   // [3072,1024]
    const float* Wout = (const float*)d_in[2];   // [1024,1024]
    float* out = (float*)d_out;                  // [2,2048,1024]

    float *qkv;
    __nv_bfloat16 *xhi, *xlo, *wqhi, *wqlo, *wohi, *wolo, *ahi, *alo;
    cudaGetSymbolAddress((void**)&qkv,  g_qkv);
    cudaGetSymbolAddress((void**)&xhi,  g_xhi);
    cudaGetSymbolAddress((void**)&xlo,  g_xlo);
    cudaGetSymbolAddress((void**)&wqhi, g_wqhi);
    cudaGetSymbolAddress((void**)&wqlo, g_wqlo);
    cudaGetSymbolAddress((void**)&wohi, g_wohi);
    cudaGetSymbolAddress((void**)&wolo, g_wolo);
    cudaGetSymbolAddress((void**)&ahi,  g_ahi);
    cudaGetSymbolAddress((void**)&alo,  g_alo);

    cudaFuncSetAttribute(gemm_mma_bf16x3, cudaFuncAttributeMaxDynamicSharedMemorySize, GSMEM);

    // Split inputs to bf16 hi/lo
    {
        int n4 = MTOT * DMODEL / 4;
        split_bf16<<<(n4 + 255) / 256, 256>>>(x, xhi, xlo, n4);
        n4 = E3 * DMODEL / 4;
        split_bf16<<<(n4 + 255) / 256, 256>>>(Wqkv, wqhi, wqlo, n4);
        n4 = TOTDIM * DMODEL / 4;
        split_bf16<<<(n4 + 255) / 256, 256>>>(Wout, wohi, wolo, n4);
    }

    // 1) qkv = x @ Wqkv^T : [4096, 3072]
    gemm_mma_bf16x3<<<dim3(E3/128, MTOT/128), 256, GSMEM>>>(xhi, xlo, wqhi, wqlo, qkv, E3, DMODEL);

    // 2) causal attention -> ahi/alo bf16 [4096, 1024]
    attn_mma<<<dim3(SEQ/64, BATCH*NHEADS), 128>>>(qkv, ahi, alo);

    // 3) out = attn @ Wout^T : [4096, 1024]
    gemm_mma_bf16x3<<<dim3(TOTDIM/128, MTOT/128), 256, GSMEM>>>(ahi, alo, wohi, wolo, out, TOTDIM, DMODEL);
}

// round 5
// speedup vs baseline: 2.7805x; 1.1232x over previous
#include <cuda_runtime.h>
#include <cuda_bf16.h>
#include <cstdint>

// Problem constants
#define BATCH 2
#define SEQ   2048
#define DMODEL 1024
#define NHEADS 16
#define DHEAD 64
#define TOTDIM 1024          // NHEADS*DHEAD
#define E3 3072              // 3*TOTDIM
#define MTOT (BATCH*SEQ)     // 4096

// ---------------------------------------------------------------------------
// Scratch (static device globals — runtime alloc is forbidden)
// ---------------------------------------------------------------------------
__device__ float g_qkv[(size_t)MTOT * E3];        // [4096,3072] fp32 (attention input)
__device__ __nv_bfloat16 g_xhi[(size_t)MTOT * DMODEL];
__device__ __nv_bfloat16 g_xlo[(size_t)MTOT * DMODEL];
__device__ __nv_bfloat16 g_wqhi[(size_t)E3 * DMODEL];
__device__ __nv_bfloat16 g_wqlo[(size_t)E3 * DMODEL];
__device__ __nv_bfloat16 g_wohi[(size_t)TOTDIM * DMODEL];
__device__ __nv_bfloat16 g_wolo[(size_t)TOTDIM * DMODEL];
__device__ __nv_bfloat16 g_ahi[(size_t)MTOT * TOTDIM];
__device__ __nv_bfloat16 g_alo[(size_t)MTOT * TOTDIM];

// ---------------------------------------------------------------------------
// Portable PTX helpers (no sm_103a-only features)
// ---------------------------------------------------------------------------
__device__ __forceinline__ uint32_t smem_to_u32(const void* p) {
    uint32_t a;
    asm("{ .reg .u64 t; cvta.to.shared.u64 t, %1; cvt.u32.u64 %0, t; }" : "=r"(a) : "l"(p));
    return a;
}

__device__ __forceinline__ void ldmx4(uint32_t* r, uint32_t addr) {
    asm volatile("ldmatrix.sync.aligned.m8n8.x4.shared.b16 {%0,%1,%2,%3}, [%4];"
        : "=r"(r[0]), "=r"(r[1]), "=r"(r[2]), "=r"(r[3]) : "r"(addr));
}

__device__ __forceinline__ void ldmx4t(uint32_t* r, uint32_t addr) {
    asm volatile("ldmatrix.sync.aligned.m8n8.x4.trans.shared.b16 {%0,%1,%2,%3}, [%4];"
        : "=r"(r[0]), "=r"(r[1]), "=r"(r[2]), "=r"(r[3]) : "r"(addr));
}

__device__ __forceinline__ void mma_bf16(float* d, const uint32_t* a, uint32_t b0, uint32_t b1) {
    asm volatile("mma.sync.aligned.m16n8k16.row.col.f32.bf16.bf16.f32 "
        "{%0,%1,%2,%3}, {%4,%5,%6,%7}, {%8,%9}, {%0,%1,%2,%3};"
        : "+f"(d[0]), "+f"(d[1]), "+f"(d[2]), "+f"(d[3])
        : "r"(a[0]), "r"(a[1]), "r"(a[2]), "r"(a[3]), "r"(b0), "r"(b1));
}

__device__ __forceinline__ void cp16(uint32_t dst, const void* src) {
    asm volatile("cp.async.cg.shared.global [%0], [%1], 16;" :: "r"(dst), "l"(src));
}
#define CP_COMMIT() asm volatile("cp.async.commit_group;" ::: "memory")
#define CP_WAIT(n)  asm volatile("cp.async.wait_group %0;" :: "n"(n) : "memory")

// Split two floats into packed bf16x2 hi + bf16x2 lo (residual)
__device__ __forceinline__ void split2(float x, float y, uint32_t& hi, uint32_t& lo) {
    __nv_bfloat16 hx = __float2bfloat16(x), hy = __float2bfloat16(y);
    float rx = x - __bfloat162float(hx), ry = y - __bfloat162float(hy);
    __nv_bfloat16 lx = __float2bfloat16(rx), ly = __float2bfloat16(ry);
    hi = ((uint32_t)*(uint16_t*)&hy << 16) | (uint32_t)*(uint16_t*)&hx;
    lo = ((uint32_t)*(uint16_t*)&ly << 16) | (uint32_t)*(uint16_t*)&lx;
}

#define SWZ(r, off) ((uint32_t)(off) ^ (uint32_t)(((r) & 7) << 4))

// ---------------------------------------------------------------------------
// Split fp32 -> bf16 (hi, lo)
// ---------------------------------------------------------------------------
__global__ void split_bf16(const float* __restrict__ src, __nv_bfloat16* __restrict__ hi,
                           __nv_bfloat16* __restrict__ lo, int n4)
{
    int i = blockIdx.x * blockDim.x + threadIdx.x;
    if (i >= n4) return;
    float4 v = ((const float4*)src)[i];
    float xs[4] = {v.x, v.y, v.z, v.w};
    __nv_bfloat16 h[4], l[4];
#pragma unroll
    for (int k = 0; k < 4; ++k) {
        h[k] = __float2bfloat16(xs[k]);
        l[k] = __float2bfloat16(xs[k] - __bfloat162float(h[k]));
    }
    ((ushort4*)hi)[i] = make_ushort4(((ushort*)h)[0], ((ushort*)h)[1], ((ushort*)h)[2], ((ushort*)h)[3]);
    ((ushort4*)lo)[i] = make_ushort4(((ushort*)l)[0], ((ushort*)l)[1], ((ushort*)l)[2], ((ushort*)l)[3]);
}

// ---------------------------------------------------------------------------
// GEMM: C = Ahi@Bhi^T + Ahi@Blo^T + Alo@Bhi^T ; 2-stage cp.async pipeline.
// A:[M,K], B:[N,K] row-major bf16. CTA tile 128x128, K-chunk 64, 8 warps.
// Smem: 2 stages x (4 tiles x [128x64] bf16) = 128 KB.
// ---------------------------------------------------------------------------
#define STAGE_BYTES 65536
#define GSMEM (2 * STAGE_BYTES)

__global__ __launch_bounds__(256, 1)
void gemm_mma_bf16x3(const __nv_bfloat16* __restrict__ Ahi, const __nv_bfloat16* __restrict__ Alo,
                     const __nv_bfloat16* __restrict__ Bhi, const __nv_bfloat16* __restrict__ Blo,
                     float* __restrict__ C, int Nn, int K)
{
    extern __shared__ char sm[];
    const uint32_t sbase = smem_to_u32(sm);

    const int tid  = threadIdx.x;
    const int wid  = tid >> 5;
    const int lane = tid & 31;
    const int warp_m = wid & 1;
    const int warp_n = wid >> 1;
    const int row0 = blockIdx.y * 128;
    const int col0 = blockIdx.x * 128;

    const __nv_bfloat16* gAhi = Ahi + (size_t)row0 * K;
    const __nv_bfloat16* gAlo = Alo + (size_t)row0 * K;
    const __nv_bfloat16* gBhi = Bhi + (size_t)col0 * K;
    const __nv_bfloat16* gBlo = Blo + (size_t)col0 * K;

    float acc[4][4][4];
#pragma unroll
    for (int m = 0; m < 4; ++m)
#pragma unroll
        for (int n = 0; n < 4; ++n)
#pragma unroll
            for (int r = 0; r < 4; ++r) acc[m][n][r] = 0.f;

    const int ld_r = lane & 15;
    const int ld_k = (lane >> 4) * 16;
    const int lrow = tid >> 3;           // 0..31
    const int lcol = (tid & 7) * 16;     // byte col

    const int nch = K / 64;

    // Issue async load of chunk c into stage s
    auto issue = [&](int c, int s) {
        const int kc = c * 64;
        const uint32_t st = sbase + (uint32_t)s * STAGE_BYTES;
#pragma unroll
        for (int i = 0; i < 4; ++i) {
            const int r = i * 32 + lrow;
            const uint32_t off = SWZ(r, r * 128 + lcol);
            const size_t gofs = (size_t)r * K + kc;
            cp16(st + off,         (const char*)(gAhi + gofs) + lcol);
            cp16(st + 16384 + off, (const char*)(gAlo + gofs) + lcol);
            cp16(st + 32768 + off, (const char*)(gBhi + gofs) + lcol);
            cp16(st + 49152 + off, (const char*)(gBlo + gofs) + lcol);
        }
        CP_COMMIT();
    };

    issue(0, 0);

    for (int c = 0; c < nch; ++c) {
        const int s = c & 1;
        if (c + 1 < nch) { issue(c + 1, (c + 1) & 1); CP_WAIT(1); }
        else             { CP_WAIT(0); }
        __syncthreads();

        const uint32_t st = sbase + (uint32_t)s * STAGE_BYTES;
#pragma unroll
        for (int ks = 0; ks < 4; ++ks) {
            uint32_t ahi[4][4], alo[4][4];
#pragma unroll
            for (int mt = 0; mt < 4; ++mt) {
                const int r = warp_m * 64 + mt * 16 + ld_r;
                uint32_t off = SWZ(r, r * 128 + ks * 32 + ld_k);
                ldmx4(ahi[mt], st + off);
                ldmx4(alo[mt], st + 16384 + off);
            }
            uint32_t bhi[2][4], blo[2][4];
#pragma unroll
            for (int nt2 = 0; nt2 < 2; ++nt2) {
                const int r = warp_n * 32 + nt2 * 16 + ld_r;
                uint32_t off = SWZ(r, r * 128 + ks * 32 + ld_k);
                ldmx4(bhi[nt2], st + 32768 + off);
                ldmx4(blo[nt2], st + 49152 + off);
            }
#pragma unroll
            for (int mt = 0; mt < 4; ++mt) {
#pragma unroll
                for (int nt = 0; nt < 4; ++nt) {
                    const int n2 = nt >> 1, nb = nt & 1;
                    mma_bf16(acc[mt][nt], ahi[mt], bhi[n2][nb], bhi[n2][nb + 2]);
                    mma_bf16(acc[mt][nt], ahi[mt], blo[n2][nb], blo[n2][nb + 2]);
                    mma_bf16(acc[mt][nt], alo[mt], bhi[n2][nb], bhi[n2][nb + 2]);
                }
            }
        }
        __syncthreads();   // stage s consumed; safe for load of chunk c+2
    }

    const int grp = lane >> 2;
    const int qid = (lane & 3) * 2;
#pragma unroll
    for (int mt = 0; mt < 4; ++mt) {
        const int gm = row0 + warp_m * 64 + mt * 16 + grp;
#pragma unroll
        for (int nt = 0; nt < 4; ++nt) {
            const int gn = col0 + warp_n * 32 + nt * 8 + qid;
            *(float2*)(C + (size_t)gm * Nn + gn)       = make_float2(acc[mt][nt][0], acc[mt][nt][1]);
            *(float2*)(C + (size_t)(gm + 8) * Nn + gn) = make_float2(acc[mt][nt][2], acc[mt][nt][3]);
        }
    }
}

// ---------------------------------------------------------------------------
// Tensor-core flash attention (causal), bf16x3 hi/lo, fp32 accum (R4, proven)
// ---------------------------------------------------------------------------
__global__ __launch_bounds__(128)
void attn_mma(const float* __restrict__ qkv,
              __nv_bfloat16* __restrict__ ahi, __nv_bfloat16* __restrict__ alo)
{
    __shared__ char sm[49152];
    const uint32_t sb = smem_to_u32(sm);
    const uint32_t oQh = 0, oQl = 8192, oKh = 16384, oKl = 24576, oVh = 32768, oVl = 40960;

    const int tid = threadIdx.x;
    const int wid = tid >> 5, lane = tid & 31;
    const int grp = lane >> 2, qid = lane & 3;
    const int qt = blockIdx.x, bh = blockIdx.y;
    const int b = bh >> 4, h = bh & 15;
    const int qb = qt * 64;
    const int qr = wid * 16;

    const float* qbase = qkv + (size_t)(b * SEQ) * E3 + h * DHEAD;
    const float* kbase = qbase + TOTDIM;
    const float* vbase = qbase + 2 * TOTDIM;

#pragma unroll
    for (int i = 0; i < 8; ++i) {
        int idx = i * 128 + tid;
        int r = idx >> 4, d0 = (idx & 15) * 4;
        float4 v = *(const float4*)(qbase + (size_t)(qb + r) * E3 + d0);
        v.x *= 0.125f; v.y *= 0.125f; v.z *= 0.125f; v.w *= 0.125f;
        uint32_t h0, l0p, h1, l1p;
        split2(v.x, v.y, h0, l0p);
        split2(v.z, v.w, h1, l1p);
        uint32_t off = SWZ(r, r * 128 + d0 * 2);
        *(uint2*)(sm + oQh + off) = make_uint2(h0, h1);
        *(uint2*)(sm + oQl + off) = make_uint2(l0p, l1p);
    }
    __syncthreads();

    uint32_t aqh[4][4], aql[4][4];
    {
        const int r = qr + (lane & 15);
        const int ch = (lane >> 4) << 4;
#pragma unroll
        for (int ks = 0; ks < 4; ++ks) {
            uint32_t off = SWZ(r, r * 128 + ks * 32 + ch);
            ldmx4(aqh[ks], sb + oQh + off);
            ldmx4(aql[ks], sb + oQl + off);
        }
    }

    float o[8][4];
#pragma unroll
    for (int nd = 0; nd < 8; ++nd)
#pragma unroll
        for (int i = 0; i < 4; ++i) o[nd][i] = 0.f;
    float m0 = -1e30f, m1 = -1e30f, l0 = 0.f, l1 = 0.f;

    for (int jt = 0; jt <= qt; ++jt) {
        const int kb = jt * 64;
        __syncthreads();
#pragma unroll
        for (int i = 0; i < 8; ++i) {
            int idx = i * 128 + tid;
            int r = idx >> 4, d0 = (idx & 15) * 4;
            uint32_t off = SWZ(r, r * 128 + d0 * 2);
            float4 kv = *(const float4*)(kbase + (size_t)(kb + r) * E3 + d0);
            uint32_t h0, l0p, h1, l1p;
            split2(kv.x, kv.y, h0, l0p);
            split2(kv.z, kv.w, h1, l1p);
            *(uint2*)(sm + oKh + off) = make_uint2(h0, h1);
            *(uint2*)(sm + oKl + off) = make_uint2(l0p, l1p);
            float4 vv = *(const float4*)(vbase + (size_t)(kb + r) * E3 + d0);
            split2(vv.x, vv.y, h0, l0p);
            split2(vv.z, vv.w, h1, l1p);
            *(uint2*)(sm + oVh + off) = make_uint2(h0, h1);
            *(uint2*)(sm + oVl + off) = make_uint2(l0p, l1p);
        }
        __syncthreads();

        float s[8][4];
#pragma unroll
        for (int nb = 0; nb < 8; ++nb)
#pragma unroll
            for (int i = 0; i < 4; ++i) s[nb][i] = 0.f;
        {
            const int rB = lane & 15;
            const int chB = (lane >> 4) << 4;
#pragma unroll
            for (int ks = 0; ks < 4; ++ks) {
                uint32_t kh[4][4], kl[4][4];
#pragma unroll
                for (int nt2 = 0; nt2 < 4; ++nt2) {
                    const int r = nt2 * 16 + rB;
                    uint32_t off = SWZ(r, r * 128 + ks * 32 + chB);
                    ldmx4(kh[nt2], sb + oKh + off);
                    ldmx4(kl[nt2], sb + oKl + off);
                }
#pragma unroll
                for (int nt2 = 0; nt2 < 4; ++nt2)
#pragma unroll
                    for (int j = 0; j < 2; ++j) {
                        const int nb = nt2 * 2 + j;
                        mma_bf16(s[nb], aqh[ks], kh[nt2][j], kh[nt2][j + 2]);
                        mma_bf16(s[nb], aqh[ks], kl[nt2][j], kl[nt2][j + 2]);
                        mma_bf16(s[nb], aql[ks], kh[nt2][j], kh[nt2][j + 2]);
                    }
            }
        }

        if (jt == qt) {
            const int row0g = qb + qr + grp;
            const int row1g = row0g + 8;
#pragma unroll
            for (int nb = 0; nb < 8; ++nb) {
                const int c0 = kb + nb * 8 + qid * 2;
                if (c0 > row0g)     s[nb][0] = -1e30f;
                if (c0 + 1 > row0g) s[nb][1] = -1e30f;
                if (c0 > row1g)     s[nb][2] = -1e30f;
                if (c0 + 1 > row1g) s[nb][3] = -1e30f;
            }
        }

        float mx0 = -1e30f, mx1 = -1e30f;
#pragma unroll
        for (int nb = 0; nb < 8; ++nb) {
            mx0 = fmaxf(mx0, fmaxf(s[nb][0], s[nb][1]));
            mx1 = fmaxf(mx1, fmaxf(s[nb][2], s[nb][3]));
        }
        mx0 = fmaxf(mx0, __shfl_xor_sync(0xffffffffu, mx0, 1));
        mx0 = fmaxf(mx0, __shfl_xor_sync(0xffffffffu, mx0, 2));
        mx1 = fmaxf(mx1, __shfl_xor_sync(0xffffffffu, mx1, 1));
        mx1 = fmaxf(mx1, __shfl_xor_sync(0xffffffffu, mx1, 2));
        const float mn0 = fmaxf(m0, mx0), mn1 = fmaxf(m1, mx1);
        const float f0 = __expf(m0 - mn0), f1 = __expf(m1 - mn1);
        m0 = mn0; m1 = mn1;
        float sum0 = 0.f, sum1 = 0.f;
#pragma unroll
        for (int nb = 0; nb < 8; ++nb) {
            s[nb][0] = __expf(s[nb][0] - m0); sum0 += s[nb][0];
            s[nb][1] = __expf(s[nb][1] - m0); sum0 += s[nb][1];
            s[nb][2] = __expf(s[nb][2] - m1); sum1 += s[nb][2];
            s[nb][3] = __expf(s[nb][3] - m1); sum1 += s[nb][3];
        }
        sum0 += __shfl_xor_sync(0xffffffffu, sum0, 1);
        sum0 += __shfl_xor_sync(0xffffffffu, sum0, 2);
        sum1 += __shfl_xor_sync(0xffffffffu, sum1, 1);
        sum1 += __shfl_xor_sync(0xffffffffu, sum1, 2);
        l0 = l0 * f0 + sum0;
        l1 = l1 * f1 + sum1;
#pragma unroll
        for (int nd = 0; nd < 8; ++nd) {
            o[nd][0] *= f0; o[nd][1] *= f0;
            o[nd][2] *= f1; o[nd][3] *= f1;
        }

        uint32_t ph[4][4], pl[4][4];
#pragma unroll
        for (int kp = 0; kp < 4; ++kp) {
            split2(s[2*kp][0],   s[2*kp][1],   ph[kp][0], pl[kp][0]);
            split2(s[2*kp][2],   s[2*kp][3],   ph[kp][1], pl[kp][1]);
            split2(s[2*kp+1][0], s[2*kp+1][1], ph[kp][2], pl[kp][2]);
            split2(s[2*kp+1][2], s[2*kp+1][3], ph[kp][3], pl[kp][3]);
        }

        {
            const int tile = lane >> 3;
            const int ta = tile & 1, ndo = tile >> 1;
            const int rl = lane & 7;
#pragma unroll
            for (int kp = 0; kp < 4; ++kp) {
#pragma unroll
                for (int ndp = 0; ndp < 4; ++ndp) {
                    const int r = kp * 16 + ta * 8 + rl;
                    uint32_t off = SWZ(r, r * 128 + (ndp * 2 + ndo) * 16);
                    uint32_t vh[4], vl[4];
                    ldmx4t(vh, sb + oVh + off);
                    ldmx4t(vl, sb + oVl + off);
                    mma_bf16(o[ndp*2],   ph[kp], vh[0], vh[1]);
                    mma_bf16(o[ndp*2],   ph[kp], vl[0], vl[1]);
                    mma_bf16(o[ndp*2],   pl[kp], vh[0], vh[1]);
                    mma_bf16(o[ndp*2+1], ph[kp], vh[2], vh[3]);
                    mma_bf16(o[ndp*2+1], ph[kp], vl[2], vl[3]);
                    mma_bf16(o[ndp*2+1], pl[kp], vh[2], vh[3]);
                }
            }
        }
    }

    const float inv0 = 1.f / l0, inv1 = 1.f / l1;
    const int row0g = qb + qr + grp;
    const size_t base0 = (size_t)(b * SEQ + row0g) * TOTDIM + h * DHEAD;
    const size_t base1 = base0 + (size_t)8 * TOTDIM;
#pragma unroll
    for (int nd = 0; nd < 8; ++nd) {
        const int col = nd * 8 + qid * 2;
        uint32_t hh, ll;
        split2(o[nd][0] * inv0, o[nd][1] * inv0, hh, ll);
        *(uint32_t*)(ahi + base0 + col) = hh;
        *(uint32_t*)(alo + base0 + col) = ll;
        split2(o[nd][2] * inv1, o[nd][3] * inv1, hh, ll);
        *(uint32_t*)(ahi + base1 + col) = hh;
        *(uint32_t*)(alo + base1 + col) = ll;
    }
}

// ---------------------------------------------------------------------------
extern "C" void kernel_launch(void* const* d_in, const int* in_sizes, int n_in,
                              void* d_out, int out_size)
{
    const float* x    = (const float*)d_in[0];   // [2,2048,1024]
    const float* Wqkv = (const float*)d_in[1];   // [3072,1024]
    const float* Wout = (const float*)d_in[2];   // [1024,1024]
    float* out = (float*)d_out;                  // [2,2048,1024]

    float *qkv;
    __nv_bfloat16 *xhi, *xlo, *wqhi, *wqlo, *wohi, *wolo, *ahi, *alo;
    cudaGetSymbolAddress((void**)&qkv,  g_qkv);
    cudaGetSymbolAddress((void**)&xhi,  g_xhi);
    cudaGetSymbolAddress((void**)&xlo,  g_xlo);
    cudaGetSymbolAddress((void**)&wqhi, g_wqhi);
    cudaGetSymbolAddress((void**)&wqlo, g_wqlo);
    cudaGetSymbolAddress((void**)&wohi, g_wohi);
    cudaGetSymbolAddress((void**)&wolo, g_wolo);
    cudaGetSymbolAddress((void**)&ahi,  g_ahi);
    cudaGetSymbolAddress((void**)&alo,  g_alo);

    cudaFuncSetAttribute(gemm_mma_bf16x3, cudaFuncAttributeMaxDynamicSharedMemorySize, GSMEM);

    // Split inputs to bf16 hi/lo
    {
        int n4 = MTOT * DMODEL / 4;
        split_bf16<<<(n4 + 255) / 256, 256>>>(x, xhi, xlo, n4);
        n4 = E3 * DMODEL / 4;
        split_bf16<<<(n4 + 255) / 256, 256>>>(Wqkv, wqhi, wqlo, n4);
        n4 = TOTDIM * DMODEL / 4;
        split_bf16<<<(n4 + 255) / 256, 256>>>(Wout, wohi, wolo, n4);
    }

    // 1) qkv = x @ Wqkv^T : [4096, 3072]
    gemm_mma_bf16x3<<<dim3(E3/128, MTOT/128), 256, GSMEM>>>(xhi, xlo, wqhi, wqlo, qkv, E3, DMODEL);

    // 2) causal attention -> ahi/alo bf16 [4096, 1024]
    attn_mma<<<dim3(SEQ/64, BATCH*NHEADS), 128>>>(qkv, ahi, alo);

    // 3) out = attn @ Wout^T : [4096, 1024]
    gemm_mma_bf16x3<<<dim3(TOTDIM/128, MTOT/128), 256, GSMEM>>>(ahi, alo, wohi, wolo, out, TOTDIM, DMODEL);
}